// round 5
// baseline (speedup 1.0000x reference)
#include <cuda_runtime.h>

// Inputs (metadata order; reference int64 narrowed to int32 by harness):
//   d_in[0]: y      float32 (T, B, 7)
//   d_in[1]: t      int32   (T, B, 3)
//   d_in[2]: y_len  int32   (B,)
// Output: float32 scalar
//
// One thread = 4 consecutive b x 2 adjacent timesteps.
// Per timestep: 7x float4 (112B contiguous) + 3x int4 -> 20 independent
// wide loads per thread front-batched for MLP. Adjacent timesteps share
// liveness, so dead threads skip everything.

#define TPB 256

__global__ void zero_out_kernel(float* out) {
    if (threadIdx.x == 0) out[0] = 0.0f;
}

__device__ __forceinline__ float ce_row(float l0, float l1, float l2,
                                        float l3, float l4,
                                        float l5, float l6,
                                        int c0, int c1, int c2)
{
    float m0 = fmaxf(l0, fmaxf(l1, l2));
    float s0 = __expf(l0 - m0) + __expf(l1 - m0) + __expf(l2 - m0);
    float sel0 = (c0 == 0) ? l0 : ((c0 == 1) ? l1 : l2);
    float r = m0 + __logf(s0) - sel0;

    float m1 = fmaxf(l3, l4);
    float s1 = __expf(l3 - m1) + __expf(l4 - m1);
    r += m1 + __logf(s1) - ((c1 == 0) ? l3 : l4);

    float m2 = fmaxf(l5, l6);
    float s2 = __expf(l5 - m2) + __expf(l6 - m2);
    r += m2 + __logf(s2) - ((c2 == 0) ? l5 : l6);
    return r;
}

__global__ __launch_bounds__(TPB)
void ce_loss_kernel(const float4* __restrict__ y4,
                    const int4* __restrict__ t4,
                    const int4* __restrict__ len4,
                    float* __restrict__ out,
                    int T, int B)
{
    const int BG  = B >> 2;                      // 128 b-groups
    const int tid = blockIdx.x * TPB + threadIdx.x;
    const int p   = tid / BG;                    // timestep pair index
    const int bg  = tid - p * BG;
    const int t0  = p << 1;
    const int t1  = t0 + 1;

    const int4 L = len4[bg];
    const int maxlen = max(max(L.x, L.y), max(L.z, L.w));

    float c0s = 0.f, c1s = 0.f, c2s = 0.f, c3s = 0.f;  // per-sample CE sums

    const bool live0 = (t0 < T) && (t0 < maxlen);
    const bool live1 = (t1 < T) && (t1 < maxlen);

    if (live0 | live1) {
        const long long e0 = (long long)t0 * B + (bg << 2);
        const long long q0 = e0 >> 2;
        const float4* ya = y4 + q0 * 7;
        const int4*   ta = t4 + q0 * 3;
        const float4* yb = ya + (B >> 2) * 7;    // next timestep: +B elements
        const int4*   tb = ta + (B >> 2) * 3;

        // front-batched loads, all independent
        float4 A0, A1, A2, A3, A4, A5, A6; int4 Ai0, Ai1, Ai2;
        float4 B0, B1, B2, B3, B4, B5, B6; int4 Bi0, Bi1, Bi2;
        if (live0) {
            A0 = ya[0]; A1 = ya[1]; A2 = ya[2]; A3 = ya[3];
            A4 = ya[4]; A5 = ya[5]; A6 = ya[6];
            Ai0 = ta[0]; Ai1 = ta[1]; Ai2 = ta[2];
        }
        if (live1) {
            B0 = yb[0]; B1 = yb[1]; B2 = yb[2]; B3 = yb[3];
            B4 = yb[4]; B5 = yb[5]; B6 = yb[6];
            Bi0 = tb[0]; Bi1 = tb[1]; Bi2 = tb[2];
        }

        if (live0) {
            if (t0 < L.x) c0s += ce_row(A0.x, A0.y, A0.z, A0.w, A1.x, A1.y, A1.z,
                                        Ai0.x, Ai0.y, Ai0.z);
            if (t0 < L.y) c1s += ce_row(A1.w, A2.x, A2.y, A2.z, A2.w, A3.x, A3.y,
                                        Ai0.w, Ai1.x, Ai1.y);
            if (t0 < L.z) c2s += ce_row(A3.z, A3.w, A4.x, A4.y, A4.z, A4.w, A5.x,
                                        Ai1.z, Ai1.w, Ai2.x);
            if (t0 < L.w) c3s += ce_row(A5.y, A5.z, A5.w, A6.x, A6.y, A6.z, A6.w,
                                        Ai2.y, Ai2.z, Ai2.w);
        }
        if (live1) {
            if (t1 < L.x) c0s += ce_row(B0.x, B0.y, B0.z, B0.w, B1.x, B1.y, B1.z,
                                        Bi0.x, Bi0.y, Bi0.z);
            if (t1 < L.y) c1s += ce_row(B1.w, B2.x, B2.y, B2.z, B2.w, B3.x, B3.y,
                                        Bi0.w, Bi1.x, Bi1.y);
            if (t1 < L.z) c2s += ce_row(B3.z, B3.w, B4.x, B4.y, B4.z, B4.w, B5.x,
                                        Bi1.z, Bi1.w, Bi2.x);
            if (t1 < L.w) c3s += ce_row(B5.y, B5.z, B5.w, B6.x, B6.y, B6.z, B6.w,
                                        Bi2.y, Bi2.z, Bi2.w);
        }
    }

    // one divide per sample (both timesteps folded)
    float contrib = 0.f;
    if (c0s != 0.f) contrib += __fdividef(c0s, (float)L.x);
    if (c1s != 0.f) contrib += __fdividef(c1s, (float)L.y);
    if (c2s != 0.f) contrib += __fdividef(c2s, (float)L.z);
    if (c3s != 0.f) contrib += __fdividef(c3s, (float)L.w);

    // warp reduce
    #pragma unroll
    for (int off = 16; off > 0; off >>= 1)
        contrib += __shfl_down_sync(0xFFFFFFFFu, contrib, off);

    __shared__ float wsum[TPB / 32];
    const int lane = threadIdx.x & 31;
    const int wid  = threadIdx.x >> 5;
    if (lane == 0) wsum[wid] = contrib;
    __syncthreads();

    if (threadIdx.x < TPB / 32) {
        float v = wsum[threadIdx.x];
        #pragma unroll
        for (int off = (TPB / 64); off > 0; off >>= 1)
            v += __shfl_down_sync(0xFFu, v, off);
        if (threadIdx.x == 0 && v != 0.0f)
            atomicAdd(out, v * (1.0f / (float)B));
    }
}

extern "C" void kernel_launch(void* const* d_in, const int* in_sizes, int n_in,
                              void* d_out, int out_size)
{
    const float4* y4   = (const float4*)d_in[0];
    const int4*   t4   = (const int4*)d_in[1];
    const int4*   len4 = (const int4*)d_in[2];
    float* out = (float*)d_out;

    const int B = in_sizes[2];                 // 512
    const int T = in_sizes[0] / (B * 7);       // 4096
    const int BG = B >> 2;                     // 128

    zero_out_kernel<<<1, 32>>>(out);

    const long long total = (long long)((T + 1) >> 1) * BG;  // 262144
    const int nblocks = (int)((total + TPB - 1) / TPB);      // 1024
    ce_loss_kernel<<<nblocks, TPB>>>(y4, t4, len4, out, T, B);
}

// round 6
// speedup vs baseline: 1.2557x; 1.2557x over previous
#include <cuda_runtime.h>

// Inputs (metadata order; reference int64 narrowed to int32 by harness):
//   d_in[0]: y      float32 (T, B, 7)
//   d_in[1]: t      int32   (T, B, 3)
//   d_in[2]: y_len  int32   (B,)
// Output: float32 scalar
//
// One thread = 4 consecutive b at one timestep t (R3 structure).
// Loads are HW-predicated (@p ld.global.nc.v4 via inline PTX) at 16B
// granularity on the liveness of the samples each sector covers, so dead
// sectors are truly never fetched (nvcc cannot speculate past @p).

#define TPB 256

__global__ void zero_out_kernel(float* out) {
    if (threadIdx.x == 0) out[0] = 0.0f;
}

__device__ __forceinline__ float ce_row(float l0, float l1, float l2,
                                        float l3, float l4,
                                        float l5, float l6,
                                        int c0, int c1, int c2)
{
    float m0 = fmaxf(l0, fmaxf(l1, l2));
    float s0 = __expf(l0 - m0) + __expf(l1 - m0) + __expf(l2 - m0);
    float sel0 = (c0 == 0) ? l0 : ((c0 == 1) ? l1 : l2);
    float r = m0 + __logf(s0) - sel0;

    float m1 = fmaxf(l3, l4);
    float s1 = __expf(l3 - m1) + __expf(l4 - m1);
    r += m1 + __logf(s1) - ((c1 == 0) ? l3 : l4);

    float m2 = fmaxf(l5, l6);
    float s2 = __expf(l5 - m2) + __expf(l6 - m2);
    r += m2 + __logf(s2) - ((c2 == 0) ? l5 : l6);
    return r;
}

// HW-predicated 16B loads: dest regs undefined when !pred (consumers are
// guarded by the same predicate, so that's safe).
__device__ __forceinline__ float4 ldp_f4(const float4* p, int pred) {
    float4 v;
    asm("{\n\t"
        ".reg .pred lp;\n\t"
        "setp.ne.s32 lp, %5, 0;\n\t"
        "@lp ld.global.nc.v4.f32 {%0,%1,%2,%3}, [%4];\n\t"
        "}"
        : "=f"(v.x), "=f"(v.y), "=f"(v.z), "=f"(v.w)
        : "l"(p), "r"(pred));
    return v;
}
__device__ __forceinline__ int4 ldp_i4(const int4* p, int pred) {
    int4 v;
    asm("{\n\t"
        ".reg .pred lp;\n\t"
        "setp.ne.s32 lp, %5, 0;\n\t"
        "@lp ld.global.nc.v4.u32 {%0,%1,%2,%3}, [%4];\n\t"
        "}"
        : "=r"(v.x), "=r"(v.y), "=r"(v.z), "=r"(v.w)
        : "l"(p), "r"(pred));
    return v;
}

__global__ __launch_bounds__(TPB)
void ce_loss_kernel(const float4* __restrict__ y4,
                    const int4* __restrict__ t4,
                    const int4* __restrict__ len4,
                    float* __restrict__ out,
                    int T, int B)
{
    const int BG  = B >> 2;
    const int tid = blockIdx.x * TPB + threadIdx.x;
    const int t   = tid / BG;
    const int bg  = tid - t * BG;

    float contrib = 0.0f;

    const int4 L = len4[bg];   // lengths for b0..b3 (L1/L2 resident)
    const int maxlen = max(max(L.x, L.y), max(L.z, L.w));

    if (t < T && t < maxlen) {
        const int a0 = t < L.x;
        const int a1 = t < L.y;
        const int a2 = t < L.z;
        const int a3 = t < L.w;

        const long long e = (long long)t * B + (bg << 2);
        const long long q = e >> 2;
        const float4* yb = y4 + q * 7;
        const int4*   tb = t4 + q * 3;

        // sector-granular predicated loads, all independent (front-batched)
        float4 v0 = ldp_f4(yb + 0, a0);
        float4 v1 = ldp_f4(yb + 1, a0 | a1);
        float4 v2 = ldp_f4(yb + 2, a1);
        float4 v3 = ldp_f4(yb + 3, a1 | a2);
        float4 v4 = ldp_f4(yb + 4, a2);
        float4 v5 = ldp_f4(yb + 5, a2 | a3);
        float4 v6 = ldp_f4(yb + 6, a3);
        int4 i0 = ldp_i4(tb + 0, a0 | a1);
        int4 i1 = ldp_i4(tb + 1, a1 | a2);
        int4 i2 = ldp_i4(tb + 2, a2 | a3);

        if (a0)
            contrib += __fdividef(
                ce_row(v0.x, v0.y, v0.z, v0.w, v1.x, v1.y, v1.z,
                       i0.x, i0.y, i0.z), (float)L.x);
        if (a1)
            contrib += __fdividef(
                ce_row(v1.w, v2.x, v2.y, v2.z, v2.w, v3.x, v3.y,
                       i0.w, i1.x, i1.y), (float)L.y);
        if (a2)
            contrib += __fdividef(
                ce_row(v3.z, v3.w, v4.x, v4.y, v4.z, v4.w, v5.x,
                       i1.z, i1.w, i2.x), (float)L.z);
        if (a3)
            contrib += __fdividef(
                ce_row(v5.y, v5.z, v5.w, v6.x, v6.y, v6.z, v6.w,
                       i2.y, i2.z, i2.w), (float)L.w);
    }

    // warp reduce
    #pragma unroll
    for (int off = 16; off > 0; off >>= 1)
        contrib += __shfl_down_sync(0xFFFFFFFFu, contrib, off);

    __shared__ float wsum[TPB / 32];
    const int lane = threadIdx.x & 31;
    const int wid  = threadIdx.x >> 5;
    if (lane == 0) wsum[wid] = contrib;
    __syncthreads();

    if (threadIdx.x < TPB / 32) {
        float v = wsum[threadIdx.x];
        #pragma unroll
        for (int off = (TPB / 64); off > 0; off >>= 1)
            v += __shfl_down_sync(0xFFu, v, off);
        if (threadIdx.x == 0 && v != 0.0f)
            atomicAdd(out, v * (1.0f / (float)B));
    }
}

extern "C" void kernel_launch(void* const* d_in, const int* in_sizes, int n_in,
                              void* d_out, int out_size)
{
    const float4* y4   = (const float4*)d_in[0];
    const int4*   t4   = (const int4*)d_in[1];
    const int4*   len4 = (const int4*)d_in[2];
    float* out = (float*)d_out;

    const int B = in_sizes[2];                 // 512
    const int T = in_sizes[0] / (B * 7);       // 4096
    const int BG = B >> 2;                     // 128

    zero_out_kernel<<<1, 32>>>(out);

    const long long total = (long long)T * BG; // 524288
    const int nblocks = (int)((total + TPB - 1) / TPB);
    ce_loss_kernel<<<nblocks, TPB>>>(y4, t4, len4, out, T, B);
}